// round 1
// baseline (speedup 1.0000x reference)
#include <cuda_runtime.h>

// MeshFit update_points_feat: per-class kNN (K=3) over block-diagonal distance
// matrix + softmax-weighted feature gather.
// Shapes (fixed): points_feat (1, C*N, D), vertices (C, N, 3), new_vertices (C, M, 3)
// C=4, N=4096, M=4096, D=32, K=3. Output (1, C*M, D) float32.

#define CC   4
#define NV   4096
#define MV   4096
#define DF   32
#define QB   128   // queries per block == threads per block

__global__ void __launch_bounds__(QB, 1)
meshfit_knn_kernel(const float* __restrict__ feat,
                   const float* __restrict__ verts,
                   const float* __restrict__ nverts,
                   float* __restrict__ out)
{
    extern __shared__ float4 pts[];   // NV float4 = 64 KB

    const int c = blockIdx.y;
    const int m = blockIdx.x * QB + threadIdx.x;

    // Cooperative load of this class's vertices into shared memory (SoA->float4).
    const float* vc = verts + (size_t)c * NV * 3;
    for (int i = threadIdx.x; i < NV; i += QB) {
        pts[i] = make_float4(vc[3 * i + 0], vc[3 * i + 1], vc[3 * i + 2], 0.0f);
    }
    __syncthreads();

    const float* q = nverts + ((size_t)c * MV + m) * 3;
    const float qx = q[0], qy = q[1], qz = q[2];

    // Running top-3 smallest (d ascending; ties keep earlier index because of
    // strict '<' and ascending scan order -> matches jax.lax.top_k tie-break).
    float d0 = 3.402823466e38f, d1 = 3.402823466e38f, d2 = 3.402823466e38f;
    int   i0 = 0, i1 = 0, i2 = 0;

#pragma unroll 4
    for (int n = 0; n < NV; ++n) {
        const float4 p = pts[n];               // broadcast LDS.128 (all lanes same addr)
        const float dx = qx - p.x;
        const float dy = qy - p.y;
        const float dz = qz - p.z;
        const float t = dx * dx + dy * dy + dz * dz;
        if (t < d2) {                           // rarely taken after warmup
            if (t < d1) {
                d2 = d1; i2 = i1;
                if (t < d0) { d1 = d0; i1 = i0; d0 = t; i0 = n; }
                else        { d1 = t;  i1 = n; }
            } else {
                d2 = t; i2 = n;
            }
        }
    }

    // Convert to global column indices of the (C*M x C*N) matrix.
    const int base = c * NV;
    int g0 = base + i0, g1 = base + i1, g2 = base + i2;

    // Off-block entries are all exactly 1.0f. The only ones that can enter the
    // top-3 (given lexicographic (value, index) tie-breaking of top_k) are the
    // three smallest off-class indices. Merge them exactly.
    const int fbase = (c == 0) ? NV : 0;
#pragma unroll
    for (int k = 0; k < 3; ++k) {
        const float fd = 1.0f;
        const int   fi = fbase + k;
        if (fd < d2 || (fd == d2 && fi < g2)) {
            d2 = fd; g2 = fi;
            if (d2 < d1 || (d2 == d1 && g2 < g1)) {
                float td = d1; d1 = d2; d2 = td;
                int   ti = g1; g1 = g2; g2 = ti;
            }
            if (d1 < d0 || (d1 == d0 && g1 < g0)) {
                float td = d0; d0 = d1; d1 = td;
                int   ti = g0; g0 = g1; g1 = ti;
            }
        }
    }

    // softmax(-d) over the 3 selected (max-subtracted, matching jax.nn.softmax).
    const float e0 = 1.0f;                 // exp(d0 - d0)
    const float e1 = expf(d0 - d1);
    const float e2 = expf(d0 - d2);
    const float inv = 1.0f / (e0 + e1 + e2);
    const float w0 = e0 * inv, w1 = e1 * inv, w2 = e2 * inv;

    // Weighted gather of the 3 neighbor feature rows (D=32 floats, 128B aligned).
    const float4* f0 = (const float4*)(feat + (size_t)g0 * DF);
    const float4* f1 = (const float4*)(feat + (size_t)g1 * DF);
    const float4* f2 = (const float4*)(feat + (size_t)g2 * DF);
    float4* o = (float4*)(out + ((size_t)c * MV + m) * DF);

#pragma unroll
    for (int dchunk = 0; dchunk < DF / 4; ++dchunk) {
        const float4 a = f0[dchunk];
        const float4 b = f1[dchunk];
        const float4 cv = f2[dchunk];
        float4 r;
        r.x = w0 * a.x + w1 * b.x + w2 * cv.x;
        r.y = w0 * a.y + w1 * b.y + w2 * cv.y;
        r.z = w0 * a.z + w1 * b.z + w2 * cv.z;
        r.w = w0 * a.w + w1 * b.w + w2 * cv.w;
        o[dchunk] = r;
    }
}

extern "C" void kernel_launch(void* const* d_in, const int* in_sizes, int n_in,
                              void* d_out, int out_size)
{
    const float* feat   = (const float*)d_in[0];  // (1, C*N, D)
    const float* verts  = (const float*)d_in[1];  // (C, N, 3)
    const float* nverts = (const float*)d_in[2];  // (C, M, 3)
    float* out = (float*)d_out;                   // (1, C*M, D)

    const int smem = NV * sizeof(float4);         // 64 KB dynamic shared
    cudaFuncSetAttribute(meshfit_knn_kernel,
                         cudaFuncAttributeMaxDynamicSharedMemorySize, smem);

    dim3 grid(MV / QB, CC);
    meshfit_knn_kernel<<<grid, QB, smem>>>(feat, verts, nverts, out);
}

// round 2
// speedup vs baseline: 2.3808x; 2.3808x over previous
#include <cuda_runtime.h>

// MeshFit update_points_feat: per-class kNN (K=3) over block-diagonal distance
// matrix + softmax-weighted feature gather.
// C=4, N=4096, M=4096, D=32, K=3. Output (1, C*M, D) float32.
//
// R1 change: 8 lanes per query (1024 threads/block) to fix occupancy
// (6.2% -> ~50%). Butterfly shfl_xor merge of per-lane top-3 with exact
// (d, idx) lexicographic ordering to preserve jax.lax.top_k tie-breaking.

#define CC    4
#define NV    4096
#define MV    4096
#define DF    32
#define SUBS  8               // lanes per query
#define QB    128             // queries per block
#define TB    (QB * SUBS)     // 1024 threads

__device__ __forceinline__ void lex_insert(float t, int ti,
                                           float& d0, float& d1, float& d2,
                                           int& i0, int& i1, int& i2)
{
    if (t < d2 || (t == d2 && ti < i2)) {
        d2 = t; i2 = ti;
        if (d2 < d1 || (d2 == d1 && i2 < i1)) {
            float td = d1; d1 = d2; d2 = td;
            int   tn = i1; i1 = i2; i2 = tn;
        }
        if (d1 < d0 || (d1 == d0 && i1 < i0)) {
            float td = d0; d0 = d1; d1 = td;
            int   tn = i0; i0 = i1; i1 = tn;
        }
    }
}

__global__ void __launch_bounds__(TB, 1)
meshfit_knn_kernel(const float* __restrict__ feat,
                   const float* __restrict__ verts,
                   const float* __restrict__ nverts,
                   float* __restrict__ out)
{
    extern __shared__ float4 pts[];   // NV float4 = 64 KB

    const int c   = blockIdx.y;
    const int tid = threadIdx.x;
    const int sub = tid & (SUBS - 1);            // lane role within query group
    const int mq  = tid >> 3;                    // query slot in block [0,QB)
    const int m   = blockIdx.x * QB + mq;        // global query index in class

    // Cooperative load of this class's vertices into shared memory.
    const float* vc = verts + (size_t)c * NV * 3;
    for (int i = tid; i < NV; i += TB) {
        pts[i] = make_float4(vc[3 * i + 0], vc[3 * i + 1], vc[3 * i + 2], 0.0f);
    }
    __syncthreads();

    const float* q = nverts + ((size_t)c * MV + m) * 3;
    const float qx = q[0], qy = q[1], qz = q[2];

    // Per-lane top-3 over the strided subsequence n = sub, sub+8, ...
    // Strict '<' + ascending n per lane keeps earliest index on ties.
    float d0 = 3.402823466e38f, d1 = 3.402823466e38f, d2 = 3.402823466e38f;
    int   i0 = 0, i1 = 0, i2 = 0;

#pragma unroll 4
    for (int n = sub; n < NV; n += SUBS) {
        const float4 p = pts[n];
        const float dx = qx - p.x;
        const float dy = qy - p.y;
        const float dz = qz - p.z;
        const float t = dx * dx + dy * dy + dz * dz;
        if (t < d2) {
            if (t < d1) {
                d2 = d1; i2 = i1;
                if (t < d0) { d1 = d0; i1 = i0; d0 = t; i0 = n; }
                else        { d1 = t;  i1 = n; }
            } else {
                d2 = t; i2 = n;
            }
        }
    }

    // Butterfly merge across the 8 lanes of this query (offsets 1,2,4 stay
    // inside the 8-lane group). Lexicographic (d, idx) compare = exact top_k.
#pragma unroll
    for (int off = 1; off < SUBS; off <<= 1) {
        const float pd0 = __shfl_xor_sync(0xffffffffu, d0, off);
        const float pd1 = __shfl_xor_sync(0xffffffffu, d1, off);
        const float pd2 = __shfl_xor_sync(0xffffffffu, d2, off);
        const int   pi0 = __shfl_xor_sync(0xffffffffu, i0, off);
        const int   pi1 = __shfl_xor_sync(0xffffffffu, i1, off);
        const int   pi2 = __shfl_xor_sync(0xffffffffu, i2, off);
        lex_insert(pd0, pi0, d0, d1, d2, i0, i1, i2);
        lex_insert(pd1, pi1, d0, d1, d2, i0, i1, i2);
        lex_insert(pd2, pi2, d0, d1, d2, i0, i1, i2);
    }

    // Global column indices of the (C*M x C*N) matrix.
    const int base = c * NV;
    int g0 = base + i0, g1 = base + i1, g2 = base + i2;

    // Off-block entries are exactly 1.0f; only the 3 smallest off-class
    // indices can enter the top-3. Merge them with the same lex order.
    const int fbase = (c == 0) ? NV : 0;
#pragma unroll
    for (int k = 0; k < 3; ++k) {
        lex_insert(1.0f, fbase + k, d0, d1, d2, g0, g1, g2);
    }

    // softmax(-d), max-subtracted (d0 is the smallest distance).
    const float e1 = expf(d0 - d1);
    const float e2 = expf(d0 - d2);
    const float inv = 1.0f / (1.0f + e1 + e2);
    const float w0 = inv, w1 = e1 * inv, w2 = e2 * inv;

    // All 8 lanes hold the identical top-3; each writes one float4 chunk.
    const float4 a  = ((const float4*)(feat + (size_t)g0 * DF))[sub];
    const float4 b  = ((const float4*)(feat + (size_t)g1 * DF))[sub];
    const float4 cv = ((const float4*)(feat + (size_t)g2 * DF))[sub];
    float4 r;
    r.x = w0 * a.x + w1 * b.x + w2 * cv.x;
    r.y = w0 * a.y + w1 * b.y + w2 * cv.y;
    r.z = w0 * a.z + w1 * b.z + w2 * cv.z;
    r.w = w0 * a.w + w1 * b.w + w2 * cv.w;
    ((float4*)(out + ((size_t)c * MV + m) * DF))[sub] = r;
}

extern "C" void kernel_launch(void* const* d_in, const int* in_sizes, int n_in,
                              void* d_out, int out_size)
{
    const float* feat   = (const float*)d_in[0];  // (1, C*N, D)
    const float* verts  = (const float*)d_in[1];  // (C, N, 3)
    const float* nverts = (const float*)d_in[2];  // (C, M, 3)
    float* out = (float*)d_out;                   // (1, C*M, D)

    const int smem = NV * sizeof(float4);         // 64 KB dynamic shared
    cudaFuncSetAttribute(meshfit_knn_kernel,
                         cudaFuncAttributeMaxDynamicSharedMemorySize, smem);

    dim3 grid(MV / QB, CC);
    meshfit_knn_kernel<<<grid, TB, smem>>>(feat, verts, nverts, out);
}